// round 17
// baseline (speedup 1.0000x reference)
#include <cuda_runtime.h>
#include <cuda_fp16.h>
#include <stdint.h>

#define N_ROWS   262144
#define TILE_M   256
#define NTHREADS 256
#define SMEM_BYTES 59392

// fp16 weights: W2 [256][128] @0, W3 [128][256] @32768, W4 [512][128] @65536
__device__ __half g_Wh[131072];

__global__ void cvt_weights_kernel(const float* __restrict__ W2,
                                   const float* __restrict__ W3,
                                   const float* __restrict__ W4) {
    int i = blockIdx.x * blockDim.x + threadIdx.x;   // 65536 threads
    if (i < 32768) {
        g_Wh[i]         = __float2half_rn(W2[i]);
        g_Wh[32768 + i] = __float2half_rn(W3[i]);
    }
    g_Wh[65536 + i] = __float2half_rn(W4[i]);
}

__device__ __forceinline__ uint32_t smem_u32(const void* p) {
    return (uint32_t)__cvta_generic_to_shared(p);
}

__device__ __forceinline__ void ldmatrix_x4(uint32_t r[4], uint32_t addr) {
    asm volatile("ldmatrix.sync.aligned.m8n8.x4.shared.b16 {%0,%1,%2,%3}, [%4];\n"
                 : "=r"(r[0]), "=r"(r[1]), "=r"(r[2]), "=r"(r[3]) : "r"(addr));
}

__device__ __forceinline__ void mma16816(float c[4], const uint32_t a[4], uint32_t b0, uint32_t b1) {
    asm volatile("mma.sync.aligned.m16n8k16.row.col.f32.f16.f16.f32 "
                 "{%0,%1,%2,%3},{%4,%5,%6,%7},{%8,%9},{%0,%1,%2,%3};\n"
                 : "+f"(c[0]), "+f"(c[1]), "+f"(c[2]), "+f"(c[3])
                 : "r"(a[0]), "r"(a[1]), "r"(a[2]), "r"(a[3]), "r"(b0), "r"(b1));
}

__device__ __forceinline__ void cp_async16(uint32_t dst_smem, const void* src) {
    asm volatile("cp.async.cg.shared.global [%0], [%1], 16;\n" :: "r"(dst_smem), "l"(src));
}
__device__ __forceinline__ void cp_commit() { asm volatile("cp.async.commit_group;\n"); }
template <int n>
__device__ __forceinline__ void cp_wait() { asm volatile("cp.async.wait_group %0;\n" :: "n"(n)); }

// tanh-GELU via MUFU.TANH: gelu(x) = 0.5x * (1 + tanh(0.79788456x + 0.03567741x^3))
__device__ __forceinline__ float fast_gelu(float x) {
    float x2 = x * x;
    float t  = fmaf(0.0356774081f, x2, 0.7978845608f);
    float z  = x * t;
    float th;
    asm("tanh.approx.f32 %0, %1;" : "=f"(th) : "f"(z));
    float hx = 0.5f * x;
    return fmaf(hx, th, hx);
}

__device__ __forceinline__ uint32_t pack_h2(float a, float b) {
    __half2 h = __floats2half2_rn(a, b);
    return *(uint32_t*)&h;
}

// ---- 16KB N-split weight chunks, swizzled ----
// ci 0-3 : W2 rows [64ci, 64ci+64) x 128K      -> [64][128],  RB=256
// ci 4-7 : W3 rows [32(ci-4), +32) x 256K      -> [32][256],  RB=512
// ci 8-15: W4 rows [64(ci-8), +64) x 128K      -> [64][128],  RB=256
__device__ __forceinline__ void prefetch_chunk(int ci, uint32_t dst, int tid) {
    if (ci < 8 ? (ci < 4) : true) {
        const __half* src = (ci < 4) ? (g_Wh + ci * 8192) : (g_Wh + 65536 + (ci - 8) * 8192);
#pragma unroll
        for (int k = 0; k < 4; ++k) {
            int i = tid + k * NTHREADS;
            int r = i >> 4, c = i & 15;
            cp_async16(dst + (uint32_t)(r * 256 + ((c ^ (r & 7)) << 4)), src + r * 128 + (c << 3));
        }
    } else {
        const __half* src = g_Wh + 32768 + (ci - 4) * 8192;
#pragma unroll
        for (int k = 0; k < 4; ++k) {
            int i = tid + k * NTHREADS;
            int r = i >> 5, c = i & 31;
            cp_async16(dst + (uint32_t)(r * 512 + ((c ^ (r & 7)) << 4)), src + r * 256 + (c << 3));
        }
    }
    cp_commit();
}

// SMEM: ring 3x16384 @0; sX @49152 (4096, 256 rows); sW1 @53248 (2048);
//       sB1 @55296 (512); sB2 @55808 (1024); sB3 @56832 (512);
//       sTok @57344 (1024); sPad @58368 (1024) => 59392
__global__ __launch_bounds__(NTHREADS, 1)
void embedder_kernel(const float* __restrict__ joint_info,
                     const int* __restrict__ joint_token,
                     const float* __restrict__ emb,
                     const float* __restrict__ W1, const float* __restrict__ b1,
                     const float* __restrict__ b2, const float* __restrict__ b3,
                     float* __restrict__ out) {
    extern __shared__ char smem[];
    const uint32_t S = smem_u32(smem);
    float4* sX  = (float4*)(smem + 49152);
    float*  sW1 = (float*)(smem + 53248);
    float*  sB1 = (float*)(smem + 55296);
    float*  sB2 = (float*)(smem + 55808);
    float*  sB3 = (float*)(smem + 56832);
    int*    sTok = (int*)(smem + 57344);
    int*    sPad = (int*)(smem + 58368);

    int tid  = threadIdx.x;
    int lane = tid & 31, warp = tid >> 5;
    int R0   = blockIdx.x * TILE_M;

    // ---- prefetch chunks 0,1 ----
    prefetch_chunk(0, S, tid);
    prefetch_chunk(1, S + 16384, tid);

    // ---- small data (256 rows) ----
    {
        float4 x = ((const float4*)joint_info)[R0 + tid];
        sX[tid]   = x;
        sTok[tid] = joint_token[R0 + tid];
        sPad[tid] = (x.x == 0.0f && x.y == 0.0f && x.z == 0.0f && x.w == 0.0f) ? 1 : 0;
    }
    if (tid < 128) {
        sB1[tid] = b1[tid];
        sB3[tid] = b3[tid];
    }
    sB2[tid] = b2[tid];
    ((float2*)sW1)[tid] = ((const float2*)W1)[tid];   // 512 floats of W1
    __syncthreads();

    // per-lane fragment coords
    int g = lane >> 2, t = lane & 3;
    int ri = lane & 7, mi = lane >> 3, sel = mi >> 1;
    int wrow = ri + ((mi & 1) << 3);
    int r0 = warp * 16;     // set 0: rows [r0, r0+16); set 1: +128

    // ---- layer 1 (K=4) scalar fp32 -> h1 A-fragments, 2 row-sets ----
    uint32_t h1A[2][8][4];
#pragma unroll
    for (int s = 0; s < 2; ++s) {
        float4 xa = sX[s * 128 + r0 + g];
        float4 xb = sX[s * 128 + r0 + g + 8];
#pragma unroll
        for (int kt = 0; kt < 8; ++kt)
#pragma unroll
            for (int j = 0; j < 2; ++j) {
                int c0 = kt * 16 + j * 8 + t * 2;
                float4 w0 = *(const float4*)&sW1[c0 * 4];
                float4 w1 = *(const float4*)&sW1[(c0 + 1) * 4];
                float bb0 = sB1[c0], bb1 = sB1[c0 + 1];
                float ya0 = fmaf(xa.x, w0.x, fmaf(xa.y, w0.y, fmaf(xa.z, w0.z, fmaf(xa.w, w0.w, bb0))));
                float ya1 = fmaf(xa.x, w1.x, fmaf(xa.y, w1.y, fmaf(xa.z, w1.z, fmaf(xa.w, w1.w, bb1))));
                float yb0 = fmaf(xb.x, w0.x, fmaf(xb.y, w0.y, fmaf(xb.z, w0.z, fmaf(xb.w, w0.w, bb0))));
                float yb1 = fmaf(xb.x, w1.x, fmaf(xb.y, w1.y, fmaf(xb.z, w1.z, fmaf(xb.w, w1.w, bb1))));
                h1A[s][kt][2 * j + 0] = pack_h2(fast_gelu(ya0), fast_gelu(ya1));
                h1A[s][kt][2 * j + 1] = pack_h2(fast_gelu(yb0), fast_gelu(yb1));
            }
    }

    // ================= layer 2: h1[2][16x128] @ W2 (4 N-chunks of 64) =================
    uint32_t h2A[2][16][4];
#pragma unroll
    for (int ci = 0; ci < 4; ++ci) {
        cp_wait<1>();
        __syncthreads();
        prefetch_chunk(ci + 2, S + (uint32_t)(((ci + 2) % 3) * 16384), tid);
        const uint32_t bb = S + (uint32_t)((ci % 3) * 16384);
#pragma unroll
        for (int j = 0; j < 4; ++j) {
            int ng = 4 * ci + j;
            int nb = ng * 16;
            float b0 = sB2[nb + 2 * t], b1v = sB2[nb + 2 * t + 1];
            float b2v = sB2[nb + 8 + 2 * t], b3v = sB2[nb + 9 + 2 * t];
            float c0[8] = {b0, b1v, b0, b1v, b2v, b3v, b2v, b3v};
            float c1[8] = {b0, b1v, b0, b1v, b2v, b3v, b2v, b3v};
            uint32_t bRow = bb + (uint32_t)((16 * j + wrow) * 256);
#pragma unroll
            for (int kt = 0; kt < 8; ++kt) {
                uint32_t B[4];
                ldmatrix_x4(B, bRow + (uint32_t)(((2 * kt + sel) ^ ri) << 4));
                mma16816(c0 + 0, h1A[0][kt], B[0], B[2]);
                mma16816(c0 + 4, h1A[0][kt], B[1], B[3]);
                mma16816(c1 + 0, h1A[1][kt], B[0], B[2]);
                mma16816(c1 + 4, h1A[1][kt], B[1], B[3]);
            }
            h2A[0][ng][0] = pack_h2(fast_gelu(c0[0]), fast_gelu(c0[1]));
            h2A[0][ng][1] = pack_h2(fast_gelu(c0[2]), fast_gelu(c0[3]));
            h2A[0][ng][2] = pack_h2(fast_gelu(c0[4]), fast_gelu(c0[5]));
            h2A[0][ng][3] = pack_h2(fast_gelu(c0[6]), fast_gelu(c0[7]));
            h2A[1][ng][0] = pack_h2(fast_gelu(c1[0]), fast_gelu(c1[1]));
            h2A[1][ng][1] = pack_h2(fast_gelu(c1[2]), fast_gelu(c1[3]));
            h2A[1][ng][2] = pack_h2(fast_gelu(c1[4]), fast_gelu(c1[5]));
            h2A[1][ng][3] = pack_h2(fast_gelu(c1[6]), fast_gelu(c1[7]));
        }
    }

    // ================= layer 3: h2[2][16x256] @ W3 (4 N-chunks of 32) =================
    uint32_t h3A[2][8][4];
#pragma unroll
    for (int ci = 4; ci < 8; ++ci) {
        cp_wait<1>();
        __syncthreads();
        prefetch_chunk(ci + 2, S + (uint32_t)(((ci + 2) % 3) * 16384), tid);
        const uint32_t bb = S + (uint32_t)((ci % 3) * 16384);
#pragma unroll
        for (int j = 0; j < 2; ++j) {
            int ng = 2 * (ci - 4) + j;
            int nb = ng * 16;
            float b0 = sB3[nb + 2 * t], b1v = sB3[nb + 2 * t + 1];
            float b2v = sB3[nb + 8 + 2 * t], b3v = sB3[nb + 9 + 2 * t];
            float c0[8] = {b0, b1v, b0, b1v, b2v, b3v, b2v, b3v};
            float c1[8] = {b0, b1v, b0, b1v, b2v, b3v, b2v, b3v};
            uint32_t bRow = bb + (uint32_t)((16 * j + wrow) * 512);
#pragma unroll
            for (int kt = 0; kt < 16; ++kt) {
                uint32_t B[4];
                ldmatrix_x4(B, bRow + (uint32_t)(((2 * kt + sel) ^ ri) << 4));
                mma16816(c0 + 0, h2A[0][kt], B[0], B[2]);
                mma16816(c0 + 4, h2A[0][kt], B[1], B[3]);
                mma16816(c1 + 0, h2A[1][kt], B[0], B[2]);
                mma16816(c1 + 4, h2A[1][kt], B[1], B[3]);
            }
            h3A[0][ng][0] = pack_h2(fast_gelu(c0[0]), fast_gelu(c0[1]));
            h3A[0][ng][1] = pack_h2(fast_gelu(c0[2]), fast_gelu(c0[3]));
            h3A[0][ng][2] = pack_h2(fast_gelu(c0[4]), fast_gelu(c0[5]));
            h3A[0][ng][3] = pack_h2(fast_gelu(c0[6]), fast_gelu(c0[7]));
            h3A[1][ng][0] = pack_h2(fast_gelu(c1[0]), fast_gelu(c1[1]));
            h3A[1][ng][1] = pack_h2(fast_gelu(c1[2]), fast_gelu(c1[3]));
            h3A[1][ng][2] = pack_h2(fast_gelu(c1[4]), fast_gelu(c1[5]));
            h3A[1][ng][3] = pack_h2(fast_gelu(c1[6]), fast_gelu(c1[7]));
        }
    }

    // ---- epilogue row constants (computed after h1A/h2A are dead) ----
    int ra0 = r0 + g, rb0 = r0 + g + 8;
    int ra1 = ra0 + 128, rb1 = rb0 + 128;
    float ma0 = sPad[ra0] ? 0.0f : 1.0f;
    float mb0 = sPad[rb0] ? 0.0f : 1.0f;
    float ma1 = sPad[ra1] ? 0.0f : 1.0f;
    float mb1 = sPad[rb1] ? 0.0f : 1.0f;
    const float* ea0 = emb + (sPad[ra0] ? 0 : sTok[ra0]) * 512;
    const float* eb0 = emb + (sPad[rb0] ? 0 : sTok[rb0]) * 512;
    const float* ea1 = emb + (sPad[ra1] ? 0 : sTok[ra1]) * 512;
    const float* eb1 = emb + (sPad[rb1] ? 0 : sTok[rb1]) * 512;
    float* oa0 = out + (size_t)(R0 + ra0) * 512;
    float* ob0 = out + (size_t)(R0 + rb0) * 512;
    float* oa1 = out + (size_t)(R0 + ra1) * 512;
    float* ob1 = out + (size_t)(R0 + rb1) * 512;

    // ================= layer 4: h3[2][16x128] @ W4 (8 N-chunks of 64) + emb/pad ======
#pragma unroll
    for (int ci = 8; ci < 16; ++ci) {
        if (ci == 15) { cp_wait<0>(); } else { cp_wait<1>(); }
        __syncthreads();
        if (ci + 2 < 16) prefetch_chunk(ci + 2, S + (uint32_t)(((ci + 2) % 3) * 16384), tid);
        const uint32_t bb = S + (uint32_t)((ci % 3) * 16384);
#pragma unroll
        for (int j = 0; j < 4; ++j) {
            uint32_t bRow = bb + (uint32_t)((16 * j + wrow) * 256);
            float c0[8] = {0, 0, 0, 0, 0, 0, 0, 0};
            float c1[8] = {0, 0, 0, 0, 0, 0, 0, 0};
#pragma unroll
            for (int kt = 0; kt < 8; ++kt) {
                uint32_t B[4];
                ldmatrix_x4(B, bRow + (uint32_t)(((2 * kt + sel) ^ ri) << 4));
                mma16816(c0 + 0, h3A[0][kt], B[0], B[2]);
                mma16816(c0 + 4, h3A[0][kt], B[1], B[3]);
                mma16816(c1 + 0, h3A[1][kt], B[0], B[2]);
                mma16816(c1 + 4, h3A[1][kt], B[1], B[3]);
            }
            int cc0 = 64 * (ci - 8) + 16 * j + 2 * t;
            int cc1 = cc0 + 8;
            float2 e, o;
            // set 0
            e = *(const float2*)(ea0 + cc0);
            o.x = fmaf(ma0, c0[0], e.x);  o.y = fmaf(ma0, c0[1], e.y);
            *(float2*)(oa0 + cc0) = o;
            e = *(const float2*)(eb0 + cc0);
            o.x = fmaf(mb0, c0[2], e.x);  o.y = fmaf(mb0, c0[3], e.y);
            *(float2*)(ob0 + cc0) = o;
            e = *(const float2*)(ea0 + cc1);
            o.x = fmaf(ma0, c0[4], e.x);  o.y = fmaf(ma0, c0[5], e.y);
            *(float2*)(oa0 + cc1) = o;
            e = *(const float2*)(eb0 + cc1);
            o.x = fmaf(mb0, c0[6], e.x);  o.y = fmaf(mb0, c0[7], e.y);
            *(float2*)(ob0 + cc1) = o;
            // set 1
            e = *(const float2*)(ea1 + cc0);
            o.x = fmaf(ma1, c1[0], e.x);  o.y = fmaf(ma1, c1[1], e.y);
            *(float2*)(oa1 + cc0) = o;
            e = *(const float2*)(eb1 + cc0);
            o.x = fmaf(mb1, c1[2], e.x);  o.y = fmaf(mb1, c1[3], e.y);
            *(float2*)(ob1 + cc0) = o;
            e = *(const float2*)(ea1 + cc1);
            o.x = fmaf(ma1, c1[4], e.x);  o.y = fmaf(ma1, c1[5], e.y);
            *(float2*)(oa1 + cc1) = o;
            e = *(const float2*)(eb1 + cc1);
            o.x = fmaf(mb1, c1[6], e.x);  o.y = fmaf(mb1, c1[7], e.y);
            *(float2*)(ob1 + cc1) = o;
        }
    }
}

extern "C" void kernel_launch(void* const* d_in, const int* in_sizes, int n_in,
                              void* d_out, int out_size) {
    const float* joint_info  = (const float*)d_in[0];
    const int*   joint_token = (const int*)d_in[1];
    const float* emb         = (const float*)d_in[2];
    const float* W1          = (const float*)d_in[3];
    const float* b1          = (const float*)d_in[4];
    const float* W2          = (const float*)d_in[5];
    const float* b2          = (const float*)d_in[6];
    const float* W3          = (const float*)d_in[7];
    const float* b3          = (const float*)d_in[8];
    const float* W4          = (const float*)d_in[9];

    cvt_weights_kernel<<<256, 256>>>(W2, W3, W4);

    cudaFuncSetAttribute(embedder_kernel,
                         cudaFuncAttributeMaxDynamicSharedMemorySize, SMEM_BYTES);
    embedder_kernel<<<N_ROWS / TILE_M, NTHREADS, SMEM_BYTES>>>(
        joint_info, joint_token, emb, W1, b1, b2, b3, (float*)d_out);
}